// round 14
// baseline (speedup 1.0000x reference)
#include <cuda_runtime.h>
#include <cuda_fp16.h>
#include <cstdint>

#define NPTS 1000000
#define WRES 64

// 4-corner blocks in fp16: per (scale, ci, y, x) one 128B-aligned block of 8
// 16B chunks. Chunk c = (h<<2)|(xp<<1)|yp holds the 8 feats [h*8..h*8+8) of
// texel (x+xp, y+yp) (clamped), in swizzled order P so that the sampling
// kernel's keep/send sets are positional (no selects):
//   P = [xp*4+yp*2, +1, xp*4+(1-yp)*2, +1, (1-xp)*4+yp*2, +1, (1-xp)*4+(1-yp)*2, +1]
// halfs per scale = 12288*H -> s0 1572864, s1 3145728, s2 6291456, s3 12582912
__device__ __align__(16) __half g_dup[23592960];

// -------- build blocks: [3,16,H,64] fp32 -> swizzled 128B corner blocks --------
__global__ void __launch_bounds__(256) build_blocks(const float* __restrict__ g0,
                                                    const float* __restrict__ g1,
                                                    const float* __restrict__ g2,
                                                    const float* __restrict__ g3) {
    int idx = blockIdx.x * blockDim.x + threadIdx.x;
    if (idx >= 368640) return;   // 3*64*(128+256+512+1024) positions
    const float* g;
    int H, toff, local, hshift;
    if (idx < 24576)       { g = g0; H = 128;  toff = 0;        local = idx;          hshift = 7;  }
    else if (idx < 73728)  { g = g1; H = 256;  toff = 1572864;  local = idx - 24576;  hshift = 8;  }
    else if (idx < 172032) { g = g2; H = 512;  toff = 4718592;  local = idx - 73728;  hshift = 9;  }
    else                   { g = g3; H = 1024; toff = 11010048; local = idx - 172032; hshift = 10; }

    int w = local & 63;
    int rest = local >> 6;            // ci*H + y
    int yy = rest & (H - 1);
    int ci = rest >> hshift;
    const float* src = g + ((size_t)(ci * 16) * H + yy) * WRES + w;
    size_t fstride = (size_t)H * WRES;
    int dx = (w < 63) ? 1 : 0;        // x+1 clamp
    int dy = (yy < H - 1) ? WRES : 0; // y+1 clamp

    __half* dst = g_dup + toff + (size_t)local * 64;
#pragma unroll
    for (int c = 0; c < 8; c++) {
        int h  = c >> 2;
        int xp = (c >> 1) & 1;
        int yp = c & 1;
        const float* s2 = src + xp * dx + yp * dy;
        int b = h * 8;
        int p0 = xp * 4 + yp * 2;
        int p2 = xp * 4 + (1 - yp) * 2;
        int p4 = (1 - xp) * 4 + yp * 2;
        int p6 = (1 - xp) * 4 + (1 - yp) * 2;
        float f0 = s2[(size_t)(b + p0) * fstride];
        float f1 = s2[(size_t)(b + p0 + 1) * fstride];
        float f2 = s2[(size_t)(b + p2) * fstride];
        float f3 = s2[(size_t)(b + p2 + 1) * fstride];
        float f4 = s2[(size_t)(b + p4) * fstride];
        float f5 = s2[(size_t)(b + p4 + 1) * fstride];
        float f6 = s2[(size_t)(b + p6) * fstride];
        float f7 = s2[(size_t)(b + p6 + 1) * fstride];
        __half2 h0 = __floats2half2_rn(f0, f1);
        __half2 h1 = __floats2half2_rn(f2, f3);
        __half2 h2 = __floats2half2_rn(f4, f5);
        __half2 h3 = __floats2half2_rn(f6, f7);
        uint4 u;
        u.x = *(uint32_t*)&h0; u.y = *(uint32_t*)&h1;
        u.z = *(uint32_t*)&h2; u.w = *(uint32_t*)&h3;
        *reinterpret_cast<uint4*>(dst + c * 8) = u;
    }
}

// -------- main sample kernel: 8 lanes per (point, ci), 4 scales per thread --------
// lane r = (h<<2)|(x<<1)|y : one LDG.128 per scale covers the whole 128B block
// across the group -> 1 L1 wavefront per sample. Combine: 2 half2 shfl (x) +
// 2 f32 shfl (y). Each lane stores 8B; group's 8 lanes = dense 64B run.
__global__ void __launch_bounds__(256) sample_k(const float* __restrict__ pts,
                                                const float* __restrict__ radius,
                                                float* __restrict__ out) {
    int t = blockIdx.x * blockDim.x + threadIdx.x;
    int G = t >> 3;               // 3M groups = (n, ci)
    int r = t & 7;
    int n = G / 3;
    int ci = G - n * 3;

    float xv = __ldg(pts + n * 3 + ci);
    float yv = __ldg(radius + n);

    float fx = (xv + 1.0f) * 31.5f;
    float x0f = floorf(fx);
    float wx = fx - x0f;
    int x0 = min(max((int)x0f, 0), 63);
    float wxr = (r & 2) ? wx : (1.0f - wx);
    float yp1 = yv + 1.0f;

    const int toffs[4] = {0, 1572864, 4718592, 11010048};
    uint4 v[4];
    float wf[4];
#pragma unroll
    for (int s = 0; s < 4; s++) {
        int H = 128 << s;
        float fy = yp1 * (0.5f * (float)(H - 1));
        float y0f = floorf(fy);
        float wy = fy - y0f;
        int y0 = min(max((int)y0f, 0), H - 1);
        float wyr = (r & 1) ? wy : (1.0f - wy);
        wf[s] = wxr * wyr;
        const __half* b = g_dup + toffs[s] + ((size_t)(ci * H + y0) * 64 + x0) * 64 + r * 8;
        v[s] = *reinterpret_cast<const uint4*>(b);
    }

    float* obase = out + (size_t)n * 192 + ci * 16 + r * 2;
#pragma unroll
    for (int s = 0; s < 4; s++) {
        const __half2* a = reinterpret_cast<const __half2*>(&v[s]);
        // keep half (feats o[0..3]) in f32; send half (o[4..7]) as half2 products
        float2 f01 = __half22float2(a[0]);
        float2 f23 = __half22float2(a[1]);
        __half2 wh2 = __float2half2_rn(wf[s]);
        __half2 s2 = __hmul2(a[2], wh2);
        __half2 s3 = __hmul2(a[3], wh2);
        uint32_t u2 = __shfl_xor_sync(0xffffffffu, *(uint32_t*)&s2, 2);
        uint32_t u3 = __shfl_xor_sync(0xffffffffu, *(uint32_t*)&s3, 2);
        float2 g01 = __half22float2(*(__half2*)&u2);
        float2 g23 = __half22float2(*(__half2*)&u3);
        float k0 = f01.x * wf[s] + g01.x;
        float k1 = f01.y * wf[s] + g01.y;
        float k2 = f23.x * wf[s] + g23.x;
        float k3 = f23.y * wf[s] + g23.y;
        float r2 = __shfl_xor_sync(0xffffffffu, k2, 1);
        float r3 = __shfl_xor_sync(0xffffffffu, k3, 1);
        *reinterpret_cast<float2*>(obase + s * 48) = make_float2(k0 + r2, k1 + r3);
    }
}

extern "C" void kernel_launch(void* const* d_in, const int* in_sizes, int n_in,
                              void* d_out, int out_size) {
    const float* pts    = (const float*)d_in[0];
    const float* radius = (const float*)d_in[1];
    float* out = (float*)d_out;

    build_blocks<<<1440, 256>>>((const float*)d_in[2],
                                (const float*)d_in[3],
                                (const float*)d_in[4],
                                (const float*)d_in[5]);

    // 3M groups * 8 lanes = 24M threads; 256/block -> 93750 blocks exactly
    sample_k<<<93750, 256>>>(pts, radius, out);
}

// round 16
// speedup vs baseline: 1.0001x; 1.0001x over previous
#include <cuda_runtime.h>
#include <cuda_fp16.h>
#include <cstdint>

#define NPTS 1000000
#define WRES 64

// 4-corner blocks in fp16: per (scale, ci, y, x) one 128B-aligned block of 8
// 16B chunks. Chunk c = (h<<2)|(xp<<1)|yp holds the 8 feats [h*8..h*8+8) of
// texel (x+xp, y+yp) (clamped), in swizzled order P so the sampler's
// keep/send sets are positional:
//   P = [xp*4+yp*2, +1, xp*4+(1-yp)*2, +1, (1-xp)*4+yp*2, +1, (1-xp)*4+(1-yp)*2, +1]
// halfs per scale = 12288*H -> offsets {0, 1572864, 4718592, 11010048}
__device__ __align__(16) __half g_dup[23592960];

__device__ __forceinline__ uint4 ldg_evict_last(const void* p, uint64_t policy) {
    uint4 v;
    asm("ld.global.nc.L2::cache_hint.v4.u32 {%0,%1,%2,%3}, [%4], %5;"
        : "=r"(v.x), "=r"(v.y), "=r"(v.z), "=r"(v.w) : "l"(p), "l"(policy));
    return v;
}

// -------- build blocks: [3,16,H,64] fp32 -> swizzled 128B corner blocks --------
__global__ void __launch_bounds__(256) build_blocks(const float* __restrict__ g0,
                                                    const float* __restrict__ g1,
                                                    const float* __restrict__ g2,
                                                    const float* __restrict__ g3) {
    int idx = blockIdx.x * blockDim.x + threadIdx.x;
    if (idx >= 368640) return;   // 3*64*(128+256+512+1024) positions
    const float* g;
    int H, toff, local, hshift;
    if (idx < 24576)       { g = g0; H = 128;  toff = 0;        local = idx;          hshift = 7;  }
    else if (idx < 73728)  { g = g1; H = 256;  toff = 1572864;  local = idx - 24576;  hshift = 8;  }
    else if (idx < 172032) { g = g2; H = 512;  toff = 4718592;  local = idx - 73728;  hshift = 9;  }
    else                   { g = g3; H = 1024; toff = 11010048; local = idx - 172032; hshift = 10; }

    int w = local & 63;
    int rest = local >> 6;            // ci*H + y
    int yy = rest & (H - 1);
    int ci = rest >> hshift;
    const float* src = g + ((size_t)(ci * 16) * H + yy) * WRES + w;
    size_t fstride = (size_t)H * WRES;
    int dx = (w < 63) ? 1 : 0;        // x+1 clamp
    int dy = (yy < H - 1) ? WRES : 0; // y+1 clamp

    __half* dst = g_dup + toff + (size_t)local * 64;
#pragma unroll
    for (int c = 0; c < 8; c++) {
        int h  = c >> 2;
        int xp = (c >> 1) & 1;
        int yp = c & 1;
        const float* s2 = src + xp * dx + yp * dy;
        int b = h * 8;
        int p0 = xp * 4 + yp * 2;
        int p2 = xp * 4 + (1 - yp) * 2;
        int p4 = (1 - xp) * 4 + yp * 2;
        int p6 = (1 - xp) * 4 + (1 - yp) * 2;
        float f0 = __ldcs(&s2[(size_t)(b + p0) * fstride]);
        float f1 = __ldcs(&s2[(size_t)(b + p0 + 1) * fstride]);
        float f2 = __ldcs(&s2[(size_t)(b + p2) * fstride]);
        float f3 = __ldcs(&s2[(size_t)(b + p2 + 1) * fstride]);
        float f4 = __ldcs(&s2[(size_t)(b + p4) * fstride]);
        float f5 = __ldcs(&s2[(size_t)(b + p4 + 1) * fstride]);
        float f6 = __ldcs(&s2[(size_t)(b + p6) * fstride]);
        float f7 = __ldcs(&s2[(size_t)(b + p6 + 1) * fstride]);
        __half2 h0 = __floats2half2_rn(f0, f1);
        __half2 h1 = __floats2half2_rn(f2, f3);
        __half2 h2 = __floats2half2_rn(f4, f5);
        __half2 h3 = __floats2half2_rn(f6, f7);
        uint4 u;
        u.x = *(uint32_t*)&h0; u.y = *(uint32_t*)&h1;
        u.z = *(uint32_t*)&h2; u.w = *(uint32_t*)&h3;
        *reinterpret_cast<uint4*>(dst + c * 8) = u;
    }
}

// -------- main sample kernel: 8 lanes per (point, ci), 4 scales per thread --------
// lane r = (h<<2)|(x<<1)|y : one LDG.128 per scale covers the whole 128B block
// across the group -> 1 L1 wavefront per sample. Grid loads pinned in L2
// (evict_last policy); output stores streamed (__stcs) so they don't thrash L2.
__global__ void __launch_bounds__(256) sample_k(const float* __restrict__ pts,
                                                const float* __restrict__ radius,
                                                float* __restrict__ out) {
    int t = blockIdx.x * blockDim.x + threadIdx.x;
    int G = t >> 3;               // 3M groups = (n, ci)
    int r = t & 7;
    int n = G / 3;
    int ci = G - n * 3;

    uint64_t pol;
    asm("createpolicy.fractional.L2::evict_last.b64 %0, 1.0;" : "=l"(pol));

    float xv = __ldg(pts + n * 3 + ci);
    float yv = __ldg(radius + n);

    float fx = (xv + 1.0f) * 31.5f;
    float x0f = floorf(fx);
    float wx = fx - x0f;
    int x0 = min(max((int)x0f, 0), 63);
    float wxr = (r & 2) ? wx : (1.0f - wx);
    float yp1 = yv + 1.0f;

    const int toffs[4] = {0, 1572864, 4718592, 11010048};
    uint4 v[4];
    float wf[4];
#pragma unroll
    for (int s = 0; s < 4; s++) {
        int H = 128 << s;
        float fy = yp1 * (0.5f * (float)(H - 1));
        float y0f = floorf(fy);
        float wy = fy - y0f;
        int y0 = min(max((int)y0f, 0), H - 1);
        float wyr = (r & 1) ? wy : (1.0f - wy);
        wf[s] = wxr * wyr;
        const __half* b = g_dup + toffs[s] + ((size_t)(ci * H + y0) * 64 + x0) * 64 + r * 8;
        v[s] = ldg_evict_last(b, pol);
    }

    float* obase = out + (size_t)n * 192 + ci * 16 + r * 2;
#pragma unroll
    for (int s = 0; s < 4; s++) {
        const __half2* a = reinterpret_cast<const __half2*>(&v[s]);
        // keep half (feats o[0..3]) in f32; send half (o[4..7]) as half2 products
        float2 f01 = __half22float2(a[0]);
        float2 f23 = __half22float2(a[1]);
        __half2 wh2 = __float2half2_rn(wf[s]);
        __half2 s2 = __hmul2(a[2], wh2);
        __half2 s3 = __hmul2(a[3], wh2);
        uint32_t u2 = __shfl_xor_sync(0xffffffffu, *(uint32_t*)&s2, 2);
        uint32_t u3 = __shfl_xor_sync(0xffffffffu, *(uint32_t*)&s3, 2);
        float2 g01 = __half22float2(*(__half2*)&u2);
        float2 g23 = __half22float2(*(__half2*)&u3);
        float k0 = f01.x * wf[s] + g01.x;
        float k1 = f01.y * wf[s] + g01.y;
        float k2 = f23.x * wf[s] + g23.x;
        float k3 = f23.y * wf[s] + g23.y;
        float r2 = __shfl_xor_sync(0xffffffffu, k2, 1);
        float r3 = __shfl_xor_sync(0xffffffffu, k3, 1);
        __stcs(reinterpret_cast<float2*>(obase + s * 48), make_float2(k0 + r2, k1 + r3));
    }
}

extern "C" void kernel_launch(void* const* d_in, const int* in_sizes, int n_in,
                              void* d_out, int out_size) {
    const float* pts    = (const float*)d_in[0];
    const float* radius = (const float*)d_in[1];
    float* out = (float*)d_out;

    build_blocks<<<1440, 256>>>((const float*)d_in[2],
                                (const float*)d_in[3],
                                (const float*)d_in[4],
                                (const float*)d_in[5]);

    // 3M groups * 8 lanes = 24M threads; 256/block -> 93750 blocks exactly
    sample_k<<<93750, 256>>>(pts, radius, out);
}